// round 2
// baseline (speedup 1.0000x reference)
#include <cuda_runtime.h>
#include <math.h>

// ---------------- problem constants ----------------
#define BATCH 8
#define CDIM 192
#define HH 64
#define WW 64
#define LTOK 4096            // HH*WW
#define TOK 32768            // BATCH*LTOK
#define HEADS 6
#define HD 32                // head dim
#define WS 8
#define NW 64                // tokens per window
#define NWIN 512             // total windows (8 * 8 * 8)
#define INCC 16              // top-k
#define HID 768              // 4*CDIM

// ---------------- scratch (device globals; no allocs) ----------------
__device__ float g_shortcut[TOK * CDIM];   // LN1 output, token-major
__device__ float g_qkv[TOK * 3 * CDIM];    // qkv, token-major [3][heads][hd]
__device__ float g_attnout[TOK * CDIM];    // attention output pre-proj
__device__ float g_x2[TOK * CDIM];         // shortcut + proj(attn)
__device__ float g_ln2[TOK * CDIM];        // LN2(x2)
__device__ float g_hidden[TOK * HID];      // gelu(fc1)
__device__ float g_x3[TOK * CDIM];         // x2 + fc2(hidden)

// ---------------- LN1: (B,C,H,W) -> token-major normalized ----------------
// one block = 32 tokens of one batch; transpose-load through smem
__global__ void ln1_kernel(const float* __restrict__ x,
                           const float* __restrict__ g,
                           const float* __restrict__ bt) {
    __shared__ float s[CDIM][33];
    __shared__ float s_mu[32], s_rs[32];
    int tile = blockIdx.x;                       // 0..1023
    int b = tile / (LTOK / 32);
    int l0 = (tile % (LTOK / 32)) * 32;
    const float* xb = x + (size_t)b * CDIM * LTOK;
    for (int idx = threadIdx.x; idx < CDIM * 32; idx += 256) {
        int c = idx >> 5, i = idx & 31;
        s[c][i] = xb[(size_t)c * LTOK + l0 + i];
    }
    __syncthreads();
    int warp = threadIdx.x >> 5, lane = threadIdx.x & 31;
    for (int i = warp; i < 32; i += 8) {
        float sum = 0.f, ss = 0.f;
        #pragma unroll
        for (int j = 0; j < 6; j++) {
            float v = s[j * 32 + lane][i];
            sum += v; ss += v * v;
        }
        #pragma unroll
        for (int o = 16; o; o >>= 1) {
            sum += __shfl_xor_sync(~0u, sum, o);
            ss  += __shfl_xor_sync(~0u, ss, o);
        }
        float mu = sum * (1.f / CDIM);
        float var = ss * (1.f / CDIM) - mu * mu;
        if (lane == 0) { s_mu[i] = mu; s_rs[i] = rsqrtf(var + 1e-5f); }
    }
    __syncthreads();
    float* out = g_shortcut + ((size_t)b * LTOK + l0) * CDIM;
    for (int idx = threadIdx.x; idx < 32 * CDIM; idx += 256) {
        int i = idx / CDIM, c = idx % CDIM;
        out[(size_t)i * CDIM + c] = (s[c][i] - s_mu[i]) * s_rs[i] * g[c] + bt[c];
    }
}

// ---------------- generic tiled GEMM: C = A(M,K) @ W(N,K)^T + bias ----------------
// EPI: 0 plain, 1 exact gelu, 2 + residual R
template <int BK, int EPI>
__global__ void gemm_kernel(const float* __restrict__ A,
                            const float* __restrict__ Wt,
                            const float* __restrict__ bias,
                            const float* __restrict__ R,
                            float* __restrict__ Cout,
                            int M, int Nn, int K) {
    const int BM = 64, BN = 64;
    __shared__ float As[BK][BM + 4];
    __shared__ float Ws[BK][BN + 4];
    int bm = blockIdx.x * BM;
    int bn = blockIdx.y * BN;
    int tid = threadIdx.x;
    int tm = tid >> 4, tn = tid & 15;           // 16x16 threads, 4x4 micro-tile
    float acc[4][4] = {};
    for (int k0 = 0; k0 < K; k0 += BK) {
        for (int idx = tid; idx < BM * BK; idx += 256) {
            int m = idx / BK, kk = idx % BK;
            As[kk][m] = A[(size_t)(bm + m) * K + k0 + kk];
        }
        for (int idx = tid; idx < BN * BK; idx += 256) {
            int n = idx / BK, kk = idx % BK;
            Ws[kk][n] = Wt[(size_t)(bn + n) * K + k0 + kk];
        }
        __syncthreads();
        #pragma unroll
        for (int kk = 0; kk < BK; kk++) {
            float a[4], w[4];
            #pragma unroll
            for (int i = 0; i < 4; i++) a[i] = As[kk][tm * 4 + i];
            #pragma unroll
            for (int j = 0; j < 4; j++) w[j] = Ws[kk][tn * 4 + j];
            #pragma unroll
            for (int i = 0; i < 4; i++)
                #pragma unroll
                for (int j = 0; j < 4; j++)
                    acc[i][j] += a[i] * w[j];
        }
        __syncthreads();
    }
    #pragma unroll
    for (int i = 0; i < 4; i++) {
        int m = bm + tm * 4 + i;
        #pragma unroll
        for (int j = 0; j < 4; j++) {
            int n = bn + tn * 4 + j;
            float v = acc[i][j] + bias[n];
            if (EPI == 1) v = 0.5f * v * (1.f + erff(v * 0.70710678118654752f));
            if (EPI == 2) v += R[(size_t)m * Nn + n];
            Cout[(size_t)m * Nn + n] = v;
        }
    }
}

// ---------------- fused window attention: one block per (window, head) ----------------
__global__ void attn_kernel(const float* __restrict__ rpb_table,
                            const float* __restrict__ temperature) {
    __shared__ float qs[NW][33], ks[NW][33], vs[NW][33];
    __shared__ float at[NW][NW];
    int win = blockIdx.x, h = blockIdx.y;
    int b = win >> 6;
    int wy = (win & 63) >> 3, wx = win & 7;
    int tid = threadIdx.x;

    // load q,k,v tiles (coalesced over head-dim)
    for (int idx = tid; idx < NW * HD; idx += 256) {
        int n = idx >> 5, d = idx & 31;
        int y = wy * 8 + (n >> 3), xx = wx * 8 + (n & 7);
        size_t t = (size_t)b * LTOK + y * WW + xx;
        const float* base = g_qkv + t * (3 * CDIM) + h * HD + d;
        qs[n][d] = base[0];
        ks[n][d] = base[CDIM];
        vs[n][d] = base[2 * CDIM];
    }
    __syncthreads();

    int warp = tid >> 5, lane = tid & 31;
    // L2-normalize rows of q and k (one warp per row, lane == head-dim)
    for (int r = warp; r < NW; r += 8) {
        float qv = qs[r][lane], kv = ks[r][lane];
        float sq = qv * qv, sk = kv * kv;
        #pragma unroll
        for (int o = 16; o; o >>= 1) {
            sq += __shfl_xor_sync(~0u, sq, o);
            sk += __shfl_xor_sync(~0u, sk, o);
        }
        qs[r][lane] = qv / fmaxf(sqrtf(sq), 1e-12f);
        ks[r][lane] = kv / fmaxf(sqrtf(sk), 1e-12f);
    }
    __syncthreads();

    float temp = temperature[h];
    // logits
    for (int idx = tid; idx < NW * NW; idx += 256) {
        int i = idx >> 6, j = idx & 63;
        float s = 0.f;
        #pragma unroll
        for (int kk = 0; kk < HD; kk++) s += qs[i][kk] * ks[j][kk];
        at[i][j] = s * temp;
    }
    __syncthreads();

    // per-row: top-16 threshold, mask, +rpb, softmax (one warp per row, 2 keys/lane)
    for (int r = warp; r < NW; r += 8) {
        float a0 = at[r][lane], a1 = at[r][lane + 32];
        float t0 = a0, t1 = a1, kth = 0.f;
        #pragma unroll
        for (int it = 0; it < INCC; it++) {
            float m = fmaxf(t0, t1);
            #pragma unroll
            for (int o = 16; o; o >>= 1) m = fmaxf(m, __shfl_xor_sync(~0u, m, o));
            kth = m;
            unsigned bal = __ballot_sync(~0u, (t0 == m) || (t1 == m));
            int src = __ffs(bal) - 1;
            if (lane == src) { if (t0 == m) t0 = -1e30f; else t1 = -1e30f; }
        }
        int ry = r >> 3, rx = r & 7;
        int j0 = lane, j1 = lane + 32;
        int i0 = ((ry - (j0 >> 3) + 7) * 15 + (rx - (j0 & 7) + 7)) * HEADS + h;
        int i1 = ((ry - (j1 >> 3) + 7) * 15 + (rx - (j1 & 7) + 7)) * HEADS + h;
        float v0 = (a0 >= kth ? a0 : -100.f) + rpb_table[i0];
        float v1 = (a1 >= kth ? a1 : -100.f) + rpb_table[i1];
        float m = fmaxf(v0, v1);
        #pragma unroll
        for (int o = 16; o; o >>= 1) m = fmaxf(m, __shfl_xor_sync(~0u, m, o));
        float e0 = __expf(v0 - m), e1 = __expf(v1 - m);
        float s = e0 + e1;
        #pragma unroll
        for (int o = 16; o; o >>= 1) s += __shfl_xor_sync(~0u, s, o);
        float inv = 1.f / s;
        at[r][lane] = e0 * inv;
        at[r][lane + 32] = e1 * inv;
    }
    __syncthreads();

    // out = attn @ v  -> token-major with c = h*HD + d
    for (int idx = tid; idx < NW * HD; idx += 256) {
        int i = idx >> 5, d = idx & 31;
        float s = 0.f;
        #pragma unroll
        for (int j = 0; j < NW; j++) s += at[i][j] * vs[j][d];
        int y = wy * 8 + (i >> 3), xx = wx * 8 + (i & 7);
        size_t t = (size_t)b * LTOK + y * WW + xx;
        g_attnout[t * CDIM + h * HD + d] = s;
    }
}

// ---------------- LN2 (token-major in/out) ----------------
__global__ void ln2_kernel(const float* __restrict__ xin,
                           const float* __restrict__ g,
                           const float* __restrict__ bt,
                           float* __restrict__ out) {
    int t = blockIdx.x * 8 + (threadIdx.x >> 5);
    int lane = threadIdx.x & 31;
    const float* row = xin + (size_t)t * CDIM;
    float v[6]; float sum = 0.f, ss = 0.f;
    #pragma unroll
    for (int j = 0; j < 6; j++) {
        v[j] = row[j * 32 + lane];
        sum += v[j]; ss += v[j] * v[j];
    }
    #pragma unroll
    for (int o = 16; o; o >>= 1) {
        sum += __shfl_xor_sync(~0u, sum, o);
        ss  += __shfl_xor_sync(~0u, ss, o);
    }
    float mu = sum * (1.f / CDIM);
    float rs = rsqrtf(ss * (1.f / CDIM) - mu * mu + 1e-5f);
    float* orow = out + (size_t)t * CDIM;
    #pragma unroll
    for (int j = 0; j < 6; j++) {
        int c = j * 32 + lane;
        orow[c] = (v[j] - mu) * rs * g[c] + bt[c];
    }
}

// ---------------- final transpose: (B,L,C) -> (B,C,L) ----------------
__global__ void transpose_kernel(const float* __restrict__ xin, float* __restrict__ out) {
    __shared__ float s[32][33];
    int l0 = blockIdx.x * 32, c0 = blockIdx.y * 32, b = blockIdx.z;
    int tx = threadIdx.x, ty = threadIdx.y;     // 32 x 8
    const float* base = xin + (size_t)b * LTOK * CDIM;
    for (int j = ty; j < 32; j += 8)
        s[j][tx] = base[(size_t)(l0 + j) * CDIM + c0 + tx];
    __syncthreads();
    float* ob = out + (size_t)b * CDIM * LTOK;
    for (int j = ty; j < 32; j += 8)
        ob[(size_t)(c0 + j) * LTOK + l0 + tx] = s[tx][j];
}

// ---------------- launch ----------------
extern "C" void kernel_launch(void* const* d_in, const int* in_sizes, int n_in,
                              void* d_out, int out_size) {
    const float* x       = (const float*)d_in[0];
    const float* norm1_g = (const float*)d_in[1];
    const float* norm1_b = (const float*)d_in[2];
    const float* qkv_w   = (const float*)d_in[3];
    const float* qkv_b   = (const float*)d_in[4];
    const float* proj_w  = (const float*)d_in[5];
    const float* proj_b  = (const float*)d_in[6];
    const float* rpb     = (const float*)d_in[7];
    const float* temp    = (const float*)d_in[8];
    const float* norm2_g = (const float*)d_in[9];
    const float* norm2_b = (const float*)d_in[10];
    const float* fc1_w   = (const float*)d_in[11];
    const float* fc1_b   = (const float*)d_in[12];
    const float* fc2_w   = (const float*)d_in[13];
    const float* fc2_b   = (const float*)d_in[14];
    float* out = (float*)d_out;

    float *p_shortcut, *p_qkv, *p_attnout, *p_x2, *p_ln2, *p_hidden, *p_x3;
    cudaGetSymbolAddress((void**)&p_shortcut, g_shortcut);
    cudaGetSymbolAddress((void**)&p_qkv,      g_qkv);
    cudaGetSymbolAddress((void**)&p_attnout,  g_attnout);
    cudaGetSymbolAddress((void**)&p_x2,       g_x2);
    cudaGetSymbolAddress((void**)&p_ln2,      g_ln2);
    cudaGetSymbolAddress((void**)&p_hidden,   g_hidden);
    cudaGetSymbolAddress((void**)&p_x3,       g_x3);

    // 1) LN1 (+ NCHW -> token-major transpose)
    ln1_kernel<<<TOK / 32, 256>>>(x, norm1_g, norm1_b);

    // 2) QKV: (T,192) @ (576,192)^T
    gemm_kernel<32, 0><<<dim3(TOK / 64, 576 / 64), 256>>>(
        p_shortcut, qkv_w, qkv_b, nullptr, p_qkv, TOK, 576, CDIM);

    // 3) windowed attention
    attn_kernel<<<dim3(NWIN, HEADS), 256>>>(rpb, temp);

    // 4) proj + residual(shortcut) -> x2
    gemm_kernel<32, 2><<<dim3(TOK / 64, CDIM / 64), 256>>>(
        p_attnout, proj_w, proj_b, p_shortcut, p_x2, TOK, CDIM, CDIM);

    // 5) LN2
    ln2_kernel<<<TOK / 8, 256>>>(p_x2, norm2_g, norm2_b, p_ln2);

    // 6) fc1 + gelu
    gemm_kernel<32, 1><<<dim3(TOK / 64, HID / 64), 256>>>(
        p_ln2, fc1_w, fc1_b, nullptr, p_hidden, TOK, HID, CDIM);

    // 7) fc2 + residual(x2)
    gemm_kernel<32, 2><<<dim3(TOK / 64, CDIM / 64), 256>>>(
        p_hidden, fc2_w, fc2_b, p_x2, p_x3, TOK, CDIM, HID);

    // 8) (B,L,C) -> (B,C,L)
    transpose_kernel<<<dim3(LTOK / 32, CDIM / 32, BATCH), dim3(32, 8)>>>(p_x3, out);
}

// round 3
// speedup vs baseline: 1.4283x; 1.4283x over previous
#include <cuda_runtime.h>
#include <math.h>
#include <stdint.h>

// ---------------- problem constants ----------------
#define BATCH 8
#define CDIM 192
#define HH 64
#define WW 64
#define LTOK 4096            // HH*WW
#define TOK 32768            // BATCH*LTOK
#define HEADS 6
#define HD 32                // head dim
#define WS 8
#define NW 64                // tokens per window
#define NWIN 512             // total windows
#define INCC 16              // top-k
#define HID 768              // 4*CDIM

// ---------------- scratch (device globals; no allocs) ----------------
__device__ float g_shortcut[TOK * CDIM];
__device__ float g_qkv[TOK * 3 * CDIM];
__device__ float g_attnout[TOK * CDIM];
__device__ float g_x2[TOK * CDIM];
__device__ float g_ln2[TOK * CDIM];
__device__ float g_hidden[TOK * HID];
__device__ float g_x3[TOK * CDIM];

// ---------------- helpers ----------------
__device__ __forceinline__ uint32_t f2tf(float v) {
    uint32_t r;
    asm("cvt.rna.tf32.f32 %0, %1;" : "=r"(r) : "f"(v));
    return r;
}

__device__ __forceinline__ void mma8(float* c, const uint32_t* a, const uint32_t* b) {
    asm volatile(
        "mma.sync.aligned.m16n8k8.row.col.f32.tf32.tf32.f32 "
        "{%0,%1,%2,%3}, {%4,%5,%6,%7}, {%8,%9}, {%0,%1,%2,%3};"
        : "+f"(c[0]), "+f"(c[1]), "+f"(c[2]), "+f"(c[3])
        : "r"(a[0]), "r"(a[1]), "r"(a[2]), "r"(a[3]), "r"(b[0]), "r"(b[1]));
}

// ---------------- LN1: (B,C,H,W) -> token-major normalized ----------------
__global__ void ln1_kernel(const float* __restrict__ x,
                           const float* __restrict__ g,
                           const float* __restrict__ bt) {
    __shared__ float s[CDIM][33];
    __shared__ float s_mu[32], s_rs[32];
    int tile = blockIdx.x;
    int b = tile / (LTOK / 32);
    int l0 = (tile % (LTOK / 32)) * 32;
    const float* xb = x + (size_t)b * CDIM * LTOK;
    for (int idx = threadIdx.x; idx < CDIM * 32; idx += 256) {
        int c = idx >> 5, i = idx & 31;
        s[c][i] = xb[(size_t)c * LTOK + l0 + i];
    }
    __syncthreads();
    int warp = threadIdx.x >> 5, lane = threadIdx.x & 31;
    for (int i = warp; i < 32; i += 8) {
        float sum = 0.f, ss = 0.f;
        #pragma unroll
        for (int j = 0; j < 6; j++) {
            float v = s[j * 32 + lane][i];
            sum += v; ss += v * v;
        }
        #pragma unroll
        for (int o = 16; o; o >>= 1) {
            sum += __shfl_xor_sync(~0u, sum, o);
            ss  += __shfl_xor_sync(~0u, ss, o);
        }
        float mu = sum * (1.f / CDIM);
        float var = ss * (1.f / CDIM) - mu * mu;
        if (lane == 0) { s_mu[i] = mu; s_rs[i] = rsqrtf(var + 1e-5f); }
    }
    __syncthreads();
    float* out = g_shortcut + ((size_t)b * LTOK + l0) * CDIM;
    for (int idx = threadIdx.x; idx < 32 * CDIM; idx += 256) {
        int i = idx / CDIM, c = idx % CDIM;
        out[(size_t)i * CDIM + c] = (s[c][i] - s_mu[i]) * s_rs[i] * g[c] + bt[c];
    }
}

// ---------------- tensor-core GEMM: C = A(M,K) @ W(N,K)^T + bias ----------------
// EPI: 0 plain, 1 exact gelu, 2 + residual R.   SPLIT: 3xTF32 (fp32-accurate).
// Block tile 128x64, 8 warps (4x2), warp tile 32x32, m16n8k8 tf32 MMA.
template <int EPI, bool SPLIT>
__global__ void __launch_bounds__(256)
tgemm(const float* __restrict__ A, const float* __restrict__ Wt,
      const float* __restrict__ bias, const float* __restrict__ R,
      float* __restrict__ Cout, int M, int Nn, int K) {
    constexpr int BM = 128, BN = 64;
    constexpr int BK = SPLIT ? 16 : 32;
    constexpr int ST = SPLIT ? 20 : 36;   // padded smem stride (conflict-free)
    __shared__ uint32_t Ah[BM * ST];
    __shared__ uint32_t Bh[BN * ST];
    __shared__ uint32_t Al[SPLIT ? BM * ST : 1];
    __shared__ uint32_t Bl[SPLIT ? BN * ST : 1];

    int bm = blockIdx.x * BM, bn = blockIdx.y * BN;
    int tid = threadIdx.x, lane = tid & 31, warp = tid >> 5;
    int wm = (warp >> 1) * 32, wn = (warp & 1) * 32;
    int g = lane >> 2, tg = lane & 3;

    float acc[2][4][4] = {};

    for (int k0 = 0; k0 < K; k0 += BK) {
        // stage A tile (128 x BK)
        for (int lin = tid; lin < BM * (BK / 4); lin += 256) {
            int row = lin / (BK / 4), c4 = lin % (BK / 4);
            float4 v = *(const float4*)(A + (size_t)(bm + row) * K + k0 + c4 * 4);
            float vv[4] = {v.x, v.y, v.z, v.w};
            #pragma unroll
            for (int j = 0; j < 4; j++) {
                uint32_t hi = f2tf(vv[j]);
                Ah[row * ST + c4 * 4 + j] = hi;
                if (SPLIT) Al[row * ST + c4 * 4 + j] = f2tf(vv[j] - __uint_as_float(hi));
            }
        }
        // stage B tile (64 x BK)
        for (int lin = tid; lin < BN * (BK / 4); lin += 256) {
            int row = lin / (BK / 4), c4 = lin % (BK / 4);
            float4 v = *(const float4*)(Wt + (size_t)(bn + row) * K + k0 + c4 * 4);
            float vv[4] = {v.x, v.y, v.z, v.w};
            #pragma unroll
            for (int j = 0; j < 4; j++) {
                uint32_t hi = f2tf(vv[j]);
                Bh[row * ST + c4 * 4 + j] = hi;
                if (SPLIT) Bl[row * ST + c4 * 4 + j] = f2tf(vv[j] - __uint_as_float(hi));
            }
        }
        __syncthreads();

        #pragma unroll
        for (int ks = 0; ks < BK / 8; ks++) {
            int k = ks * 8;
            uint32_t ah[2][4], al[2][4], bh[4][2], bl[4][2];
            #pragma unroll
            for (int mi = 0; mi < 2; mi++) {
                int r = wm + mi * 16;
                ah[mi][0] = Ah[(r + g) * ST + k + tg];
                ah[mi][1] = Ah[(r + g + 8) * ST + k + tg];
                ah[mi][2] = Ah[(r + g) * ST + k + tg + 4];
                ah[mi][3] = Ah[(r + g + 8) * ST + k + tg + 4];
                if (SPLIT) {
                    al[mi][0] = Al[(r + g) * ST + k + tg];
                    al[mi][1] = Al[(r + g + 8) * ST + k + tg];
                    al[mi][2] = Al[(r + g) * ST + k + tg + 4];
                    al[mi][3] = Al[(r + g + 8) * ST + k + tg + 4];
                }
            }
            #pragma unroll
            for (int ni = 0; ni < 4; ni++) {
                int n = wn + ni * 8;
                bh[ni][0] = Bh[(n + g) * ST + k + tg];
                bh[ni][1] = Bh[(n + g) * ST + k + tg + 4];
                if (SPLIT) {
                    bl[ni][0] = Bl[(n + g) * ST + k + tg];
                    bl[ni][1] = Bl[(n + g) * ST + k + tg + 4];
                }
            }
            #pragma unroll
            for (int mi = 0; mi < 2; mi++)
                #pragma unroll
                for (int ni = 0; ni < 4; ni++) {
                    mma8(acc[mi][ni], ah[mi], bh[ni]);
                    if (SPLIT) {
                        mma8(acc[mi][ni], ah[mi], bl[ni]);
                        mma8(acc[mi][ni], al[mi], bh[ni]);
                    }
                }
        }
        __syncthreads();
    }

    // epilogue
    #pragma unroll
    for (int mi = 0; mi < 2; mi++) {
        #pragma unroll
        for (int ni = 0; ni < 4; ni++) {
            int r0 = bm + wm + mi * 16 + g;
            int c = bn + wn + ni * 8 + tg * 2;
            float bz0 = bias[c], bz1 = bias[c + 1];
            #pragma unroll
            for (int rr = 0; rr < 2; rr++) {
                int m = r0 + rr * 8;
                float v0 = acc[mi][ni][rr * 2 + 0] + bz0;
                float v1 = acc[mi][ni][rr * 2 + 1] + bz1;
                if (EPI == 1) {
                    v0 = 0.5f * v0 * (1.f + erff(v0 * 0.70710678118654752f));
                    v1 = 0.5f * v1 * (1.f + erff(v1 * 0.70710678118654752f));
                }
                if (EPI == 2) {
                    v0 += R[(size_t)m * Nn + c];
                    v1 += R[(size_t)m * Nn + c + 1];
                }
                Cout[(size_t)m * Nn + c] = v0;
                Cout[(size_t)m * Nn + c + 1] = v1;
            }
        }
    }
}

// ---------------- fused window attention: one block per (window, head) ----------------
__global__ void attn_kernel(const float* __restrict__ rpb_table,
                            const float* __restrict__ temperature) {
    __shared__ float qs[NW][33], ks[NW][33], vs[NW][33];
    __shared__ float at[NW][NW];
    int win = blockIdx.x, h = blockIdx.y;
    int b = win >> 6;
    int wy = (win & 63) >> 3, wx = win & 7;
    int tid = threadIdx.x;

    for (int idx = tid; idx < NW * HD; idx += 256) {
        int n = idx >> 5, d = idx & 31;
        int y = wy * 8 + (n >> 3), xx = wx * 8 + (n & 7);
        size_t t = (size_t)b * LTOK + y * WW + xx;
        const float* base = g_qkv + t * (3 * CDIM) + h * HD + d;
        qs[n][d] = base[0];
        ks[n][d] = base[CDIM];
        vs[n][d] = base[2 * CDIM];
    }
    __syncthreads();

    int warp = tid >> 5, lane = tid & 31;
    for (int r = warp; r < NW; r += 8) {
        float qv = qs[r][lane], kv = ks[r][lane];
        float sq = qv * qv, sk = kv * kv;
        #pragma unroll
        for (int o = 16; o; o >>= 1) {
            sq += __shfl_xor_sync(~0u, sq, o);
            sk += __shfl_xor_sync(~0u, sk, o);
        }
        qs[r][lane] = qv / fmaxf(sqrtf(sq), 1e-12f);
        ks[r][lane] = kv / fmaxf(sqrtf(sk), 1e-12f);
    }
    __syncthreads();

    float temp = temperature[h];
    for (int idx = tid; idx < NW * NW; idx += 256) {
        int i = idx >> 6, j = idx & 63;
        float s = 0.f;
        #pragma unroll
        for (int kk = 0; kk < HD; kk++) s += qs[i][kk] * ks[j][kk];
        at[i][j] = s * temp;
    }
    __syncthreads();

    for (int r = warp; r < NW; r += 8) {
        float a0 = at[r][lane], a1 = at[r][lane + 32];
        float t0 = a0, t1 = a1, kth = 0.f;
        #pragma unroll
        for (int it = 0; it < INCC; it++) {
            float m = fmaxf(t0, t1);
            #pragma unroll
            for (int o = 16; o; o >>= 1) m = fmaxf(m, __shfl_xor_sync(~0u, m, o));
            kth = m;
            unsigned bal = __ballot_sync(~0u, (t0 == m) || (t1 == m));
            int src = __ffs(bal) - 1;
            if (lane == src) { if (t0 == m) t0 = -1e30f; else t1 = -1e30f; }
        }
        int ry = r >> 3, rx = r & 7;
        int j0 = lane, j1 = lane + 32;
        int i0 = ((ry - (j0 >> 3) + 7) * 15 + (rx - (j0 & 7) + 7)) * HEADS + h;
        int i1 = ((ry - (j1 >> 3) + 7) * 15 + (rx - (j1 & 7) + 7)) * HEADS + h;
        float v0 = (a0 >= kth ? a0 : -100.f) + rpb_table[i0];
        float v1 = (a1 >= kth ? a1 : -100.f) + rpb_table[i1];
        float m = fmaxf(v0, v1);
        #pragma unroll
        for (int o = 16; o; o >>= 1) m = fmaxf(m, __shfl_xor_sync(~0u, m, o));
        float e0 = __expf(v0 - m), e1 = __expf(v1 - m);
        float s = e0 + e1;
        #pragma unroll
        for (int o = 16; o; o >>= 1) s += __shfl_xor_sync(~0u, s, o);
        float inv = 1.f / s;
        at[r][lane] = e0 * inv;
        at[r][lane + 32] = e1 * inv;
    }
    __syncthreads();

    for (int idx = tid; idx < NW * HD; idx += 256) {
        int i = idx >> 5, d = idx & 31;
        float s = 0.f;
        #pragma unroll
        for (int j = 0; j < NW; j++) s += at[i][j] * vs[j][d];
        int y = wy * 8 + (i >> 3), xx = wx * 8 + (i & 7);
        size_t t = (size_t)b * LTOK + y * WW + xx;
        g_attnout[t * CDIM + h * HD + d] = s;
    }
}

// ---------------- LN2 ----------------
__global__ void ln2_kernel(const float* __restrict__ xin,
                           const float* __restrict__ g,
                           const float* __restrict__ bt,
                           float* __restrict__ out) {
    int t = blockIdx.x * 8 + (threadIdx.x >> 5);
    int lane = threadIdx.x & 31;
    const float* row = xin + (size_t)t * CDIM;
    float v[6]; float sum = 0.f, ss = 0.f;
    #pragma unroll
    for (int j = 0; j < 6; j++) {
        v[j] = row[j * 32 + lane];
        sum += v[j]; ss += v[j] * v[j];
    }
    #pragma unroll
    for (int o = 16; o; o >>= 1) {
        sum += __shfl_xor_sync(~0u, sum, o);
        ss  += __shfl_xor_sync(~0u, ss, o);
    }
    float mu = sum * (1.f / CDIM);
    float rs = rsqrtf(ss * (1.f / CDIM) - mu * mu + 1e-5f);
    float* orow = out + (size_t)t * CDIM;
    #pragma unroll
    for (int j = 0; j < 6; j++) {
        int c = j * 32 + lane;
        orow[c] = (v[j] - mu) * rs * g[c] + bt[c];
    }
}

// ---------------- final transpose: (B,L,C) -> (B,C,L) ----------------
__global__ void transpose_kernel(const float* __restrict__ xin, float* __restrict__ out) {
    __shared__ float s[32][33];
    int l0 = blockIdx.x * 32, c0 = blockIdx.y * 32, b = blockIdx.z;
    int tx = threadIdx.x, ty = threadIdx.y;
    const float* base = xin + (size_t)b * LTOK * CDIM;
    for (int j = ty; j < 32; j += 8)
        s[j][tx] = base[(size_t)(l0 + j) * CDIM + c0 + tx];
    __syncthreads();
    float* ob = out + (size_t)b * CDIM * LTOK;
    for (int j = ty; j < 32; j += 8)
        ob[(size_t)(c0 + j) * LTOK + l0 + tx] = s[tx][j];
}

// ---------------- launch ----------------
extern "C" void kernel_launch(void* const* d_in, const int* in_sizes, int n_in,
                              void* d_out, int out_size) {
    const float* x       = (const float*)d_in[0];
    const float* norm1_g = (const float*)d_in[1];
    const float* norm1_b = (const float*)d_in[2];
    const float* qkv_w   = (const float*)d_in[3];
    const float* qkv_b   = (const float*)d_in[4];
    const float* proj_w  = (const float*)d_in[5];
    const float* proj_b  = (const float*)d_in[6];
    const float* rpb     = (const float*)d_in[7];
    const float* temp    = (const float*)d_in[8];
    const float* norm2_g = (const float*)d_in[9];
    const float* norm2_b = (const float*)d_in[10];
    const float* fc1_w   = (const float*)d_in[11];
    const float* fc1_b   = (const float*)d_in[12];
    const float* fc2_w   = (const float*)d_in[13];
    const float* fc2_b   = (const float*)d_in[14];
    float* out = (float*)d_out;

    float *p_shortcut, *p_qkv, *p_attnout, *p_x2, *p_ln2, *p_hidden, *p_x3;
    cudaGetSymbolAddress((void**)&p_shortcut, g_shortcut);
    cudaGetSymbolAddress((void**)&p_qkv,      g_qkv);
    cudaGetSymbolAddress((void**)&p_attnout,  g_attnout);
    cudaGetSymbolAddress((void**)&p_x2,       g_x2);
    cudaGetSymbolAddress((void**)&p_ln2,      g_ln2);
    cudaGetSymbolAddress((void**)&p_hidden,   g_hidden);
    cudaGetSymbolAddress((void**)&p_x3,       g_x3);

    // 1) LN1 (+ NCHW -> token-major)
    ln1_kernel<<<TOK / 32, 256>>>(x, norm1_g, norm1_b);

    // 2) QKV: 3xTF32 split (fp32-accurate -> stable top-k ordering)
    tgemm<0, true><<<dim3(TOK / 128, 576 / 64), 256>>>(
        p_shortcut, qkv_w, qkv_b, nullptr, p_qkv, TOK, 576, CDIM);

    // 3) windowed attention
    attn_kernel<<<dim3(NWIN, HEADS), 256>>>(rpb, temp);

    // 4) proj + residual(shortcut) -> x2  (plain tf32)
    tgemm<2, false><<<dim3(TOK / 128, CDIM / 64), 256>>>(
        p_attnout, proj_w, proj_b, p_shortcut, p_x2, TOK, CDIM, CDIM);

    // 5) LN2
    ln2_kernel<<<TOK / 8, 256>>>(p_x2, norm2_g, norm2_b, p_ln2);

    // 6) fc1 + gelu (plain tf32)
    tgemm<1, false><<<dim3(TOK / 128, HID / 64), 256>>>(
        p_ln2, fc1_w, fc1_b, nullptr, p_hidden, TOK, HID, CDIM);

    // 7) fc2 + residual(x2) (plain tf32)
    tgemm<2, false><<<dim3(TOK / 128, CDIM / 64), 256>>>(
        p_hidden, fc2_w, fc2_b, p_x2, p_x3, TOK, CDIM, HID);

    // 8) (B,L,C) -> (B,C,L)
    transpose_kernel<<<dim3(LTOK / 32, CDIM / 32, BATCH), dim3(32, 8)>>>(p_x3, out);
}

// round 4
// speedup vs baseline: 1.7655x; 1.2360x over previous
#include <cuda_runtime.h>
#include <math.h>
#include <stdint.h>

// ---------------- problem constants ----------------
#define BATCH 8
#define CDIM 192
#define HH 64
#define WW 64
#define LTOK 4096
#define TOK 32768
#define HEADS 6
#define HD 32
#define WS 8
#define NW 64
#define NWIN 512
#define INCC 16
#define HID 768

// ---------------- scratch ----------------
__device__ float g_shortcut[TOK * CDIM];
__device__ float g_qkv[TOK * 3 * CDIM];
__device__ float g_attnout[TOK * CDIM];
__device__ float g_x2[TOK * CDIM];
__device__ float g_ln2[TOK * CDIM];
__device__ float g_hidden[TOK * HID];

// ---------------- helpers ----------------
__device__ __forceinline__ uint32_t f2tf(float v) {
    uint32_t r;
    asm("cvt.rna.tf32.f32 %0, %1;" : "=r"(r) : "f"(v));
    return r;
}
__device__ __forceinline__ void mma8(float* c, const uint32_t* a, const uint32_t* b) {
    asm volatile(
        "mma.sync.aligned.m16n8k8.row.col.f32.tf32.tf32.f32 "
        "{%0,%1,%2,%3}, {%4,%5,%6,%7}, {%8,%9}, {%0,%1,%2,%3};"
        : "+f"(c[0]), "+f"(c[1]), "+f"(c[2]), "+f"(c[3])
        : "r"(a[0]), "r"(a[1]), "r"(a[2]), "r"(a[3]), "r"(b[0]), "r"(b[1]));
}
__device__ __forceinline__ void cp16(void* smem, const void* g) {
    uint32_t a = (uint32_t)__cvta_generic_to_shared(smem);
    asm volatile("cp.async.cg.shared.global [%0], [%1], 16;" :: "r"(a), "l"(g));
}
__device__ __forceinline__ void cp_commit() { asm volatile("cp.async.commit_group;"); }
template <int N>
__device__ __forceinline__ void cp_wait() { asm volatile("cp.async.wait_group %0;" :: "n"(N)); }

// ---------------- LN1: (B,C,H,W) -> token-major normalized ----------------
__global__ void ln1_kernel(const float* __restrict__ x,
                           const float* __restrict__ g,
                           const float* __restrict__ bt) {
    __shared__ float s[CDIM][33];
    __shared__ float s_mu[32], s_rs[32];
    int tile = blockIdx.x;
    int b = tile / (LTOK / 32);
    int l0 = (tile % (LTOK / 32)) * 32;
    const float* xb = x + (size_t)b * CDIM * LTOK;
    for (int idx = threadIdx.x; idx < CDIM * 32; idx += 256) {
        int c = idx >> 5, i = idx & 31;
        s[c][i] = xb[(size_t)c * LTOK + l0 + i];
    }
    __syncthreads();
    int warp = threadIdx.x >> 5, lane = threadIdx.x & 31;
    for (int i = warp; i < 32; i += 8) {
        float sum = 0.f, ss = 0.f;
        #pragma unroll
        for (int j = 0; j < 6; j++) {
            float v = s[j * 32 + lane][i];
            sum += v; ss += v * v;
        }
        #pragma unroll
        for (int o = 16; o; o >>= 1) {
            sum += __shfl_xor_sync(~0u, sum, o);
            ss  += __shfl_xor_sync(~0u, ss, o);
        }
        float mu = sum * (1.f / CDIM);
        float var = ss * (1.f / CDIM) - mu * mu;
        if (lane == 0) { s_mu[i] = mu; s_rs[i] = rsqrtf(var + 1e-5f); }
    }
    __syncthreads();
    float* out = g_shortcut + ((size_t)b * LTOK + l0) * CDIM;
    for (int idx = threadIdx.x; idx < 32 * CDIM; idx += 256) {
        int i = idx / CDIM, c = idx % CDIM;
        out[(size_t)i * CDIM + c] = (s[c][i] - s_mu[i]) * s_rs[i] * g[c] + bt[c];
    }
}

// ---------------- pipelined tensor-core GEMM: C = A(M,K) @ W(N,K)^T + bias -----
// EPI: 0 plain, 1 gelu, 2 +R, 3 +R then write transposed (B,C,L).
// SPLIT: 3xTF32 hi/lo (fp32-accurate). 3-stage cp.async pipeline, BK=16.
template <int EPI, bool SPLIT>
__global__ void __launch_bounds__(256)
tgemm(const float* __restrict__ A, const float* __restrict__ Wt,
      const float* __restrict__ bias, const float* __restrict__ R,
      float* __restrict__ Cout, int M, int Nn, int K) {
    constexpr int BM = 128, BN = 64, BK = 16, ST = 20, STG = 3;
    __shared__ float As[STG][BM * ST];
    __shared__ float Bs[STG][BN * ST];

    int bm = blockIdx.x * BM, bn = blockIdx.y * BN;
    int tid = threadIdx.x, lane = tid & 31, warp = tid >> 5;
    int wm = (warp >> 1) * 32, wn = (warp & 1) * 32;
    int g = lane >> 2, tg = lane & 3;

    float acc[2][4][4] = {};
    int KT = K / BK;

    auto load_stage = [&](int s, int k0) {
        #pragma unroll
        for (int t = tid; t < BM * (BK / 4); t += 256) {
            int row = t >> 2, c4 = t & 3;
            cp16(&As[s][row * ST + c4 * 4], A + (size_t)(bm + row) * K + k0 + c4 * 4);
        }
        {
            int t = tid;
            if (t < BN * (BK / 4)) {
                int row = t >> 2, c4 = t & 3;
                cp16(&Bs[s][row * ST + c4 * 4], Wt + (size_t)(bn + row) * K + k0 + c4 * 4);
            }
        }
    };

    #pragma unroll
    for (int s = 0; s < STG - 1; s++) {
        if (s < KT) load_stage(s, s * BK);
        cp_commit();
    }

    for (int kt = 0; kt < KT; kt++) {
        cp_wait<STG - 2>();
        __syncthreads();
        int pf = kt + STG - 1;
        if (pf < KT) load_stage(pf % STG, pf * BK);
        cp_commit();

        const float* as = As[kt % STG];
        const float* bs = Bs[kt % STG];
        #pragma unroll
        for (int ks = 0; ks < 2; ks++) {
            int k = ks * 8;
            uint32_t ah[2][4], bh[4][2];
            uint32_t al[2][4], bl[4][2];
            #pragma unroll
            for (int mi = 0; mi < 2; mi++) {
                int r = wm + mi * 16;
                float v0 = as[(r + g) * ST + k + tg];
                float v1 = as[(r + g + 8) * ST + k + tg];
                float v2 = as[(r + g) * ST + k + tg + 4];
                float v3 = as[(r + g + 8) * ST + k + tg + 4];
                if (SPLIT) {
                    ah[mi][0] = f2tf(v0); al[mi][0] = f2tf(v0 - __uint_as_float(ah[mi][0]));
                    ah[mi][1] = f2tf(v1); al[mi][1] = f2tf(v1 - __uint_as_float(ah[mi][1]));
                    ah[mi][2] = f2tf(v2); al[mi][2] = f2tf(v2 - __uint_as_float(ah[mi][2]));
                    ah[mi][3] = f2tf(v3); al[mi][3] = f2tf(v3 - __uint_as_float(ah[mi][3]));
                } else {
                    ah[mi][0] = __float_as_uint(v0); ah[mi][1] = __float_as_uint(v1);
                    ah[mi][2] = __float_as_uint(v2); ah[mi][3] = __float_as_uint(v3);
                }
            }
            #pragma unroll
            for (int ni = 0; ni < 4; ni++) {
                int n = wn + ni * 8;
                float w0 = bs[(n + g) * ST + k + tg];
                float w1 = bs[(n + g) * ST + k + tg + 4];
                if (SPLIT) {
                    bh[ni][0] = f2tf(w0); bl[ni][0] = f2tf(w0 - __uint_as_float(bh[ni][0]));
                    bh[ni][1] = f2tf(w1); bl[ni][1] = f2tf(w1 - __uint_as_float(bh[ni][1]));
                } else {
                    bh[ni][0] = __float_as_uint(w0); bh[ni][1] = __float_as_uint(w1);
                }
            }
            #pragma unroll
            for (int mi = 0; mi < 2; mi++)
                #pragma unroll
                for (int ni = 0; ni < 4; ni++) {
                    mma8(acc[mi][ni], ah[mi], bh[ni]);
                    if (SPLIT) {
                        mma8(acc[mi][ni], ah[mi], bl[ni]);
                        mma8(acc[mi][ni], al[mi], bh[ni]);
                    }
                }
        }
    }

    // epilogue
    #pragma unroll
    for (int mi = 0; mi < 2; mi++) {
        #pragma unroll
        for (int ni = 0; ni < 4; ni++) {
            int r0 = bm + wm + mi * 16 + g;
            int c = bn + wn + ni * 8 + tg * 2;
            float bz0 = bias[c], bz1 = bias[c + 1];
            #pragma unroll
            for (int rr = 0; rr < 2; rr++) {
                int m = r0 + rr * 8;
                float v0 = acc[mi][ni][rr * 2 + 0] + bz0;
                float v1 = acc[mi][ni][rr * 2 + 1] + bz1;
                if (EPI == 1) {
                    v0 = 0.5f * v0 * (1.f + erff(v0 * 0.70710678118654752f));
                    v1 = 0.5f * v1 * (1.f + erff(v1 * 0.70710678118654752f));
                }
                if (EPI == 2 || EPI == 3) {
                    v0 += R[(size_t)m * Nn + c];
                    v1 += R[(size_t)m * Nn + c + 1];
                }
                if (EPI == 3) {
                    int b = m >> 12, l = m & 4095;
                    Cout[((size_t)b * CDIM + c) * LTOK + l] = v0;
                    Cout[((size_t)b * CDIM + c + 1) * LTOK + l] = v1;
                } else {
                    Cout[(size_t)m * Nn + c] = v0;
                    Cout[(size_t)m * Nn + c + 1] = v1;
                }
            }
        }
    }
}

// ---------------- fused window attention: one block per (window, head) ----------------
__global__ void attn_kernel(const float* __restrict__ rpb_table,
                            const float* __restrict__ temperature) {
    __shared__ float qs[NW][33], ks[NW][33], vs[NW][33];
    __shared__ float at[NW][NW];
    int win = blockIdx.x, h = blockIdx.y;
    int b = win >> 6;
    int wy = (win & 63) >> 3, wx = win & 7;
    int tid = threadIdx.x;

    for (int idx = tid; idx < NW * HD; idx += 256) {
        int n = idx >> 5, d = idx & 31;
        int y = wy * 8 + (n >> 3), xx = wx * 8 + (n & 7);
        size_t t = (size_t)b * LTOK + y * WW + xx;
        const float* base = g_qkv + t * (3 * CDIM) + h * HD + d;
        qs[n][d] = base[0];
        ks[n][d] = base[CDIM];
        vs[n][d] = base[2 * CDIM];
    }
    __syncthreads();

    int warp = tid >> 5, lane = tid & 31;
    for (int r = warp; r < NW; r += 8) {
        float qv = qs[r][lane], kv = ks[r][lane];
        float sq = qv * qv, sk = kv * kv;
        #pragma unroll
        for (int o = 16; o; o >>= 1) {
            sq += __shfl_xor_sync(~0u, sq, o);
            sk += __shfl_xor_sync(~0u, sk, o);
        }
        qs[r][lane] = qv / fmaxf(sqrtf(sq), 1e-12f);
        ks[r][lane] = kv / fmaxf(sqrtf(sk), 1e-12f);
    }
    __syncthreads();

    float temp = temperature[h];
    for (int idx = tid; idx < NW * NW; idx += 256) {
        int i = idx >> 6, j = idx & 63;
        float s = 0.f;
        #pragma unroll
        for (int kk = 0; kk < HD; kk++) s += qs[i][kk] * ks[j][kk];
        at[i][j] = s * temp;
    }
    __syncthreads();

    for (int r = warp; r < NW; r += 8) {
        float a0 = at[r][lane], a1 = at[r][lane + 32];
        float t0 = a0, t1 = a1, kth = 0.f;
        #pragma unroll
        for (int it = 0; it < INCC; it++) {
            float m = fmaxf(t0, t1);
            #pragma unroll
            for (int o = 16; o; o >>= 1) m = fmaxf(m, __shfl_xor_sync(~0u, m, o));
            kth = m;
            unsigned bal = __ballot_sync(~0u, (t0 == m) || (t1 == m));
            int src = __ffs(bal) - 1;
            if (lane == src) { if (t0 == m) t0 = -1e30f; else t1 = -1e30f; }
        }
        int ry = r >> 3, rx = r & 7;
        int j0 = lane, j1 = lane + 32;
        int i0 = ((ry - (j0 >> 3) + 7) * 15 + (rx - (j0 & 7) + 7)) * HEADS + h;
        int i1 = ((ry - (j1 >> 3) + 7) * 15 + (rx - (j1 & 7) + 7)) * HEADS + h;
        float v0 = (a0 >= kth ? a0 : -100.f) + rpb_table[i0];
        float v1 = (a1 >= kth ? a1 : -100.f) + rpb_table[i1];
        float m = fmaxf(v0, v1);
        #pragma unroll
        for (int o = 16; o; o >>= 1) m = fmaxf(m, __shfl_xor_sync(~0u, m, o));
        float e0 = __expf(v0 - m), e1 = __expf(v1 - m);
        float s = e0 + e1;
        #pragma unroll
        for (int o = 16; o; o >>= 1) s += __shfl_xor_sync(~0u, s, o);
        float inv = 1.f / s;
        at[r][lane] = e0 * inv;
        at[r][lane + 32] = e1 * inv;
    }
    __syncthreads();

    for (int idx = tid; idx < NW * HD; idx += 256) {
        int i = idx >> 5, d = idx & 31;
        float s = 0.f;
        #pragma unroll
        for (int j = 0; j < NW; j++) s += at[i][j] * vs[j][d];
        int y = wy * 8 + (i >> 3), xx = wx * 8 + (i & 7);
        size_t t = (size_t)b * LTOK + y * WW + xx;
        g_attnout[t * CDIM + h * HD + d] = s;
    }
}

// ---------------- LN2 ----------------
__global__ void ln2_kernel(const float* __restrict__ xin,
                           const float* __restrict__ g,
                           const float* __restrict__ bt,
                           float* __restrict__ out) {
    int t = blockIdx.x * 8 + (threadIdx.x >> 5);
    int lane = threadIdx.x & 31;
    const float* row = xin + (size_t)t * CDIM;
    float v[6]; float sum = 0.f, ss = 0.f;
    #pragma unroll
    for (int j = 0; j < 6; j++) {
        v[j] = row[j * 32 + lane];
        sum += v[j]; ss += v[j] * v[j];
    }
    #pragma unroll
    for (int o = 16; o; o >>= 1) {
        sum += __shfl_xor_sync(~0u, sum, o);
        ss  += __shfl_xor_sync(~0u, ss, o);
    }
    float mu = sum * (1.f / CDIM);
    float rs = rsqrtf(ss * (1.f / CDIM) - mu * mu + 1e-5f);
    float* orow = out + (size_t)t * CDIM;
    #pragma unroll
    for (int j = 0; j < 6; j++) {
        int c = j * 32 + lane;
        orow[c] = (v[j] - mu) * rs * g[c] + bt[c];
    }
}

// ---------------- launch ----------------
extern "C" void kernel_launch(void* const* d_in, const int* in_sizes, int n_in,
                              void* d_out, int out_size) {
    const float* x       = (const float*)d_in[0];
    const float* norm1_g = (const float*)d_in[1];
    const float* norm1_b = (const float*)d_in[2];
    const float* qkv_w   = (const float*)d_in[3];
    const float* qkv_b   = (const float*)d_in[4];
    const float* proj_w  = (const float*)d_in[5];
    const float* proj_b  = (const float*)d_in[6];
    const float* rpb     = (const float*)d_in[7];
    const float* temp    = (const float*)d_in[8];
    const float* norm2_g = (const float*)d_in[9];
    const float* norm2_b = (const float*)d_in[10];
    const float* fc1_w   = (const float*)d_in[11];
    const float* fc1_b   = (const float*)d_in[12];
    const float* fc2_w   = (const float*)d_in[13];
    const float* fc2_b   = (const float*)d_in[14];
    float* out = (float*)d_out;

    float *p_shortcut, *p_qkv, *p_attnout, *p_x2, *p_ln2, *p_hidden;
    cudaGetSymbolAddress((void**)&p_shortcut, g_shortcut);
    cudaGetSymbolAddress((void**)&p_qkv,      g_qkv);
    cudaGetSymbolAddress((void**)&p_attnout,  g_attnout);
    cudaGetSymbolAddress((void**)&p_x2,       g_x2);
    cudaGetSymbolAddress((void**)&p_ln2,      g_ln2);
    cudaGetSymbolAddress((void**)&p_hidden,   g_hidden);

    // 1) LN1 (+ NCHW -> token-major)
    ln1_kernel<<<TOK / 32, 256>>>(x, norm1_g, norm1_b);

    // 2) QKV (3xTF32 split: fp32-accurate -> stable top-k)
    tgemm<0, true><<<dim3(TOK / 128, 576 / 64), 256>>>(
        p_shortcut, qkv_w, qkv_b, nullptr, p_qkv, TOK, 576, CDIM);

    // 3) windowed attention
    attn_kernel<<<dim3(NWIN, HEADS), 256>>>(rpb, temp);

    // 4) proj + residual(shortcut) -> x2
    tgemm<2, false><<<dim3(TOK / 128, CDIM / 64), 256>>>(
        p_attnout, proj_w, proj_b, p_shortcut, p_x2, TOK, CDIM, CDIM);

    // 5) LN2
    ln2_kernel<<<TOK / 8, 256>>>(p_x2, norm2_g, norm2_b, p_ln2);

    // 6) fc1 + gelu
    tgemm<1, false><<<dim3(TOK / 128, HID / 64), 256>>>(
        p_ln2, fc1_w, fc1_b, nullptr, p_hidden, TOK, HID, CDIM);

    // 7) fc2 + residual(x2), fused transpose to (B,C,L)
    tgemm<3, false><<<dim3(TOK / 128, CDIM / 64), 256>>>(
        p_hidden, fc2_w, fc2_b, p_x2, out, TOK, CDIM, HID);
}

// round 6
// speedup vs baseline: 2.2320x; 1.2643x over previous
#include <cuda_runtime.h>
#include <math.h>
#include <stdint.h>

// ---------------- problem constants ----------------
#define BATCH 8
#define CDIM 192
#define HH 64
#define WW 64
#define LTOK 4096
#define TOK 32768
#define HEADS 6
#define HD 32
#define WS 8
#define NW 64
#define NWIN 512
#define INCC 16
#define HID 768

// ---------------- scratch ----------------
__device__ float g_shortcut[TOK * CDIM];
__device__ float g_qkv[TOK * 3 * CDIM];
__device__ float g_attnout[TOK * CDIM];
__device__ float g_x2[TOK * CDIM];
__device__ float g_ln2[TOK * CDIM];
__device__ float g_hidden[TOK * HID];

// ---------------- helpers ----------------
__device__ __forceinline__ uint32_t f2tf(float v) {
    uint32_t r;
    asm("cvt.rna.tf32.f32 %0, %1;" : "=r"(r) : "f"(v));
    return r;
}
__device__ __forceinline__ void mma8(float* c, const uint32_t* a, const uint32_t* b) {
    asm volatile(
        "mma.sync.aligned.m16n8k8.row.col.f32.tf32.tf32.f32 "
        "{%0,%1,%2,%3}, {%4,%5,%6,%7}, {%8,%9}, {%0,%1,%2,%3};"
        : "+f"(c[0]), "+f"(c[1]), "+f"(c[2]), "+f"(c[3])
        : "r"(a[0]), "r"(a[1]), "r"(a[2]), "r"(a[3]), "r"(b[0]), "r"(b[1]));
}
__device__ __forceinline__ void ldsm4(uint32_t* r, const float* p) {
    uint32_t a = (uint32_t)__cvta_generic_to_shared(p);
    asm volatile("ldmatrix.sync.aligned.m8n8.x4.shared.b16 {%0,%1,%2,%3}, [%4];"
                 : "=r"(r[0]), "=r"(r[1]), "=r"(r[2]), "=r"(r[3]) : "r"(a));
}
__device__ __forceinline__ void cp16(void* smem, const void* g) {
    uint32_t a = (uint32_t)__cvta_generic_to_shared(smem);
    asm volatile("cp.async.cg.shared.global [%0], [%1], 16;" :: "r"(a), "l"(g));
}
__device__ __forceinline__ void cp_commit() { asm volatile("cp.async.commit_group;"); }
template <int N>
__device__ __forceinline__ void cp_wait() { asm volatile("cp.async.wait_group %0;" :: "n"(N)); }

// ---------------- LN1: (B,C,H,W) -> token-major normalized ----------------
__global__ void ln1_kernel(const float* __restrict__ x,
                           const float* __restrict__ g,
                           const float* __restrict__ bt) {
    __shared__ float s[CDIM][33];
    __shared__ float s_mu[32], s_rs[32];
    int tile = blockIdx.x;
    int b = tile / (LTOK / 32);
    int l0 = (tile % (LTOK / 32)) * 32;
    const float* xb = x + (size_t)b * CDIM * LTOK;
    for (int idx = threadIdx.x; idx < CDIM * 32; idx += 256) {
        int c = idx >> 5, i = idx & 31;
        s[c][i] = xb[(size_t)c * LTOK + l0 + i];
    }
    __syncthreads();
    int warp = threadIdx.x >> 5, lane = threadIdx.x & 31;
    for (int i = warp; i < 32; i += 8) {
        float sum = 0.f, ss = 0.f;
        #pragma unroll
        for (int j = 0; j < 6; j++) {
            float v = s[j * 32 + lane][i];
            sum += v; ss += v * v;
        }
        #pragma unroll
        for (int o = 16; o; o >>= 1) {
            sum += __shfl_xor_sync(~0u, sum, o);
            ss  += __shfl_xor_sync(~0u, ss, o);
        }
        float mu = sum * (1.f / CDIM);
        float var = ss * (1.f / CDIM) - mu * mu;
        if (lane == 0) { s_mu[i] = mu; s_rs[i] = rsqrtf(var + 1e-5f); }
    }
    __syncthreads();
    float* out = g_shortcut + ((size_t)b * LTOK + l0) * CDIM;
    for (int idx = threadIdx.x; idx < 32 * CDIM; idx += 256) {
        int i = idx / CDIM, c = idx % CDIM;
        out[(size_t)i * CDIM + c] = (s[c][i] - s_mu[i]) * s_rs[i] * g[c] + bt[c];
    }
}

// ---------------- pipelined tensor-core GEMM, ldmatrix fragments -------------
// EPI: 0 plain, 1 gelu, 2 +R, 3 +R then write transposed (B,C,L).
// SPLIT: 3xTF32 hi/lo (fp32-accurate).
template <int EPI, bool SPLIT>
__global__ void __launch_bounds__(256)
tgemm(const float* __restrict__ A, const float* __restrict__ Wt,
      const float* __restrict__ bias, const float* __restrict__ R,
      float* __restrict__ Cout, int M, int Nn, int K) {
    constexpr int BM = 128, BN = 64, BK = 16, ST = 20, STG = 3;
    __shared__ float As[STG][BM * ST];
    __shared__ float Bs[STG][BN * ST];

    int bm = blockIdx.x * BM, bn = blockIdx.y * BN;
    int tid = threadIdx.x, lane = tid & 31, warp = tid >> 5;
    int wm = (warp >> 1) * 32, wn = (warp & 1) * 32;
    int g = lane >> 2, tg = lane & 3;
    int l15 = lane & 15, lhi = lane >> 4;          // A-frag addressing
    int l7 = (lane & 7) + 8 * (lane >> 4);         // B-frag row
    int bko = 4 * ((lane >> 3) & 1);               // B-frag k offset

    float acc[2][4][4] = {};
    int KT = K / BK;

    auto load_stage = [&](int s, int k0) {
        #pragma unroll
        for (int t = tid; t < BM * (BK / 4); t += 256) {
            int row = t >> 2, c4 = t & 3;
            cp16(&As[s][row * ST + c4 * 4], A + (size_t)(bm + row) * K + k0 + c4 * 4);
        }
        {
            int row = tid >> 2, c4 = tid & 3;
            cp16(&Bs[s][row * ST + c4 * 4], Wt + (size_t)(bn + row) * K + k0 + c4 * 4);
        }
    };

    #pragma unroll
    for (int s = 0; s < STG - 1; s++) {
        if (s < KT) load_stage(s, s * BK);
        cp_commit();
    }

    for (int kt = 0; kt < KT; kt++) {
        cp_wait<STG - 2>();
        __syncthreads();
        int pf = kt + STG - 1;
        if (pf < KT) load_stage(pf % STG, pf * BK);
        cp_commit();

        const float* as = As[kt % STG];
        const float* bs = Bs[kt % STG];
        #pragma unroll
        for (int ks = 0; ks < 2; ks++) {
            int k = ks * 8;
            uint32_t ar[2][4], br[2][4];
            #pragma unroll
            for (int mi = 0; mi < 2; mi++)
                ldsm4(ar[mi], &as[(wm + mi * 16 + l15) * ST + k + 4 * lhi]);
            #pragma unroll
            for (int nb = 0; nb < 2; nb++)
                ldsm4(br[nb], &bs[(wn + nb * 16 + l7) * ST + k + bko]);

            uint32_t ah[2][4], al[2][4], bh[2][4], bl[2][4];
            if (SPLIT) {
                #pragma unroll
                for (int mi = 0; mi < 2; mi++)
                    #pragma unroll
                    for (int j = 0; j < 4; j++) {
                        float v = __uint_as_float(ar[mi][j]);
                        ah[mi][j] = f2tf(v);
                        al[mi][j] = f2tf(v - __uint_as_float(ah[mi][j]));
                    }
                #pragma unroll
                for (int nb = 0; nb < 2; nb++)
                    #pragma unroll
                    for (int j = 0; j < 4; j++) {
                        float v = __uint_as_float(br[nb][j]);
                        bh[nb][j] = f2tf(v);
                        bl[nb][j] = f2tf(v - __uint_as_float(bh[nb][j]));
                    }
            }
            #pragma unroll
            for (int mi = 0; mi < 2; mi++)
                #pragma unroll
                for (int ni = 0; ni < 4; ni++) {
                    int nb = ni >> 1, e = (ni & 1) * 2;
                    if (SPLIT) {
                        uint32_t b2h[2] = {bh[nb][e], bh[nb][e + 1]};
                        uint32_t b2l[2] = {bl[nb][e], bl[nb][e + 1]};
                        mma8(acc[mi][ni], ah[mi], b2h);
                        mma8(acc[mi][ni], ah[mi], b2l);
                        mma8(acc[mi][ni], al[mi], b2h);
                    } else {
                        uint32_t b2[2] = {br[nb][e], br[nb][e + 1]};
                        mma8(acc[mi][ni], ar[mi], b2);
                    }
                }
        }
    }

    // epilogue
    #pragma unroll
    for (int mi = 0; mi < 2; mi++) {
        #pragma unroll
        for (int ni = 0; ni < 4; ni++) {
            int r0 = bm + wm + mi * 16 + g;
            int c = bn + wn + ni * 8 + tg * 2;
            float bz0 = bias[c], bz1 = bias[c + 1];
            #pragma unroll
            for (int rr = 0; rr < 2; rr++) {
                int m = r0 + rr * 8;
                float v0 = acc[mi][ni][rr * 2 + 0] + bz0;
                float v1 = acc[mi][ni][rr * 2 + 1] + bz1;
                if (EPI == 1) {
                    v0 = 0.5f * v0 * (1.f + erff(v0 * 0.70710678118654752f));
                    v1 = 0.5f * v1 * (1.f + erff(v1 * 0.70710678118654752f));
                }
                if (EPI == 2 || EPI == 3) {
                    v0 += R[(size_t)m * Nn + c];
                    v1 += R[(size_t)m * Nn + c + 1];
                }
                if (EPI == 3) {
                    int b = m >> 12, l = m & 4095;
                    Cout[((size_t)b * CDIM + c) * LTOK + l] = v0;
                    Cout[((size_t)b * CDIM + c + 1) * LTOK + l] = v1;
                } else {
                    Cout[(size_t)m * Nn + c] = v0;
                    Cout[(size_t)m * Nn + c + 1] = v1;
                }
            }
        }
    }
}

// ---------------- tensor-core window attention: block per (window, head) -----
// S = l2n(Q) @ l2n(K)^T * temp via split-3xTF32 (fp32-accurate for stable topk)
// O = P @ V via rna-tf32 mma
__global__ void __launch_bounds__(256) attn_kernel(const float* __restrict__ rpb_table,
                                                   const float* __restrict__ temperature) {
    __shared__ float qs[NW * 36], ks[NW * 36];
    __shared__ float vst[HD * 68];       // V transposed: [d][key]
    __shared__ float at[NW * 68];        // V staging, then S / P
    int win = blockIdx.x, h = blockIdx.y;
    int b = win >> 6;
    int wy = (win & 63) >> 3, wx = win & 7;
    int tid = threadIdx.x, lane = tid & 31, warp = tid >> 5;
    int g = lane >> 2, tg = lane & 3;
    int l15 = lane & 15, lhi = lane >> 4;
    int l7 = (lane & 7) + 8 * (lane >> 4);
    int bko = 4 * ((lane >> 3) & 1);

    // load q,k ([n][d], stride 36) + v into at ([n][d], stride 68)
    for (int idx = tid; idx < NW * HD; idx += 256) {
        int n = idx >> 5, d = idx & 31;
        int y = wy * 8 + (n >> 3), xx = wx * 8 + (n & 7);
        size_t t = (size_t)b * LTOK + y * WW + xx;
        const float* base = g_qkv + t * (3 * CDIM) + h * HD + d;
        qs[n * 36 + d] = base[0];
        ks[n * 36 + d] = base[CDIM];
        at[n * 68 + d] = base[2 * CDIM];
    }
    __syncthreads();

    // l2-normalize q,k rows
    for (int r = warp; r < NW; r += 8) {
        float qv = qs[r * 36 + lane], kv = ks[r * 36 + lane];
        float sq = qv * qv, sk = kv * kv;
        #pragma unroll
        for (int o = 16; o; o >>= 1) {
            sq += __shfl_xor_sync(~0u, sq, o);
            sk += __shfl_xor_sync(~0u, sk, o);
        }
        qs[r * 36 + lane] = qv / fmaxf(sqrtf(sq), 1e-12f);
        ks[r * 36 + lane] = kv / fmaxf(sqrtf(sk), 1e-12f);
    }
    // transpose v: at[n][d] -> vst[d][n]
    for (int idx = tid; idx < NW * HD; idx += 256) {
        int n = idx & 63, d = idx >> 6;
        vst[d * 68 + n] = at[n * 68 + d];
    }
    __syncthreads();

    float temp = temperature[h];
    // S mma: warp tile m16 x n32
    {
        int wm = (warp >> 1) * 16, wn = (warp & 1) * 32;
        float acc[4][4] = {};
        #pragma unroll
        for (int kc = 0; kc < 4; kc++) {
            int k = kc * 8;
            uint32_t ar[4], br[2][4];
            ldsm4(ar, &qs[(wm + l15) * 36 + k + 4 * lhi]);
            #pragma unroll
            for (int nb = 0; nb < 2; nb++)
                ldsm4(br[nb], &ks[(wn + nb * 16 + l7) * 36 + k + bko]);
            uint32_t ah[4], al[4], bh[2][4], bl[2][4];
            #pragma unroll
            for (int j = 0; j < 4; j++) {
                float v = __uint_as_float(ar[j]);
                ah[j] = f2tf(v);
                al[j] = f2tf(v - __uint_as_float(ah[j]));
            }
            #pragma unroll
            for (int nb = 0; nb < 2; nb++)
                #pragma unroll
                for (int j = 0; j < 4; j++) {
                    float v = __uint_as_float(br[nb][j]);
                    bh[nb][j] = f2tf(v);
                    bl[nb][j] = f2tf(v - __uint_as_float(bh[nb][j]));
                }
            #pragma unroll
            for (int ni = 0; ni < 4; ni++) {
                int nb = ni >> 1, e = (ni & 1) * 2;
                uint32_t b2h[2] = {bh[nb][e], bh[nb][e + 1]};
                uint32_t b2l[2] = {bl[nb][e], bl[nb][e + 1]};
                mma8(acc[ni], ah, b2h);
                mma8(acc[ni], ah, b2l);
                mma8(acc[ni], al, b2h);
            }
        }
        #pragma unroll
        for (int ni = 0; ni < 4; ni++) {
            float* p0 = &at[(wm + g) * 68 + wn + ni * 8 + tg * 2];
            float* p1 = &at[(wm + g + 8) * 68 + wn + ni * 8 + tg * 2];
            p0[0] = acc[ni][0] * temp; p0[1] = acc[ni][1] * temp;
            p1[0] = acc[ni][2] * temp; p1[1] = acc[ni][3] * temp;
        }
    }
    __syncthreads();

    // per-row top-16 threshold, mask, +rpb, softmax
    for (int r = warp; r < NW; r += 8) {
        float a0 = at[r * 68 + lane], a1 = at[r * 68 + lane + 32];
        float t0 = a0, t1 = a1, kth = 0.f;
        #pragma unroll
        for (int it = 0; it < INCC; it++) {
            float m = fmaxf(t0, t1);
            #pragma unroll
            for (int o = 16; o; o >>= 1) m = fmaxf(m, __shfl_xor_sync(~0u, m, o));
            kth = m;
            unsigned bal = __ballot_sync(~0u, (t0 == m) || (t1 == m));
            int src = __ffs(bal) - 1;
            if (lane == src) { if (t0 == m) t0 = -1e30f; else t1 = -1e30f; }
        }
        int ry = r >> 3, rx = r & 7;
        int j0 = lane, j1 = lane + 32;
        int i0 = ((ry - (j0 >> 3) + 7) * 15 + (rx - (j0 & 7) + 7)) * HEADS + h;
        int i1 = ((ry - (j1 >> 3) + 7) * 15 + (rx - (j1 & 7) + 7)) * HEADS + h;
        float v0 = (a0 >= kth ? a0 : -100.f) + rpb_table[i0];
        float v1 = (a1 >= kth ? a1 : -100.f) + rpb_table[i1];
        float m = fmaxf(v0, v1);
        #pragma unroll
        for (int o = 16; o; o >>= 1) m = fmaxf(m, __shfl_xor_sync(~0u, m, o));
        float e0 = __expf(v0 - m), e1 = __expf(v1 - m);
        float s = e0 + e1;
        #pragma unroll
        for (int o = 16; o; o >>= 1) s += __shfl_xor_sync(~0u, s, o);
        float inv = 1.f / s;
        at[r * 68 + lane] = e0 * inv;
        at[r * 68 + lane + 32] = e1 * inv;
    }
    __syncthreads();

    // O = P @ V : warp tile m16 x n16, k=64
    {
        int mt = warp >> 1, nh = (warp & 1) * 16;
        float acc[2][4] = {};
        #pragma unroll
        for (int kc = 0; kc < 8; kc++) {
            int k = kc * 8;
            uint32_t ar[4], br[4], af[4], bf[4];
            ldsm4(ar, &at[(mt * 16 + l15) * 68 + k + 4 * lhi]);
            ldsm4(br, &vst[(nh + l7) * 68 + k + bko]);
            #pragma unroll
            for (int j = 0; j < 4; j++) {
                af[j] = f2tf(__uint_as_float(ar[j]));
                bf[j] = f2tf(__uint_as_float(br[j]));
            }
            uint32_t b20[2] = {bf[0], bf[1]};
            uint32_t b21[2] = {bf[2], bf[3]};
            mma8(acc[0], af, b20);
            mma8(acc[1], af, b21);
        }
        #pragma unroll
        for (int ni = 0; ni < 2; ni++) {
            int c = h * HD + nh + ni * 8 + tg * 2;
            #pragma unroll
            for (int rr = 0; rr < 2; rr++) {
                int m = mt * 16 + g + rr * 8;
                int y = wy * 8 + (m >> 3), xx = wx * 8 + (m & 7);
                size_t t = (size_t)b * LTOK + y * WW + xx;
                g_attnout[t * CDIM + c]     = acc[ni][rr * 2];
                g_attnout[t * CDIM + c + 1] = acc[ni][rr * 2 + 1];
            }
        }
    }
}

// ---------------- LN2 ----------------
__global__ void ln2_kernel(const float* __restrict__ xin,
                           const float* __restrict__ g,
                           const float* __restrict__ bt,
                           float* __restrict__ out) {
    int t = blockIdx.x * 8 + (threadIdx.x >> 5);
    int lane = threadIdx.x & 31;
    const float* row = xin + (size_t)t * CDIM;
    float v[6]; float sum = 0.f, ss = 0.f;
    #pragma unroll
    for (int j = 0; j < 6; j++) {
        v[j] = row[j * 32 + lane];
        sum += v[j]; ss += v[j] * v[j];
    }
    #pragma unroll
    for (int o = 16; o; o >>= 1) {
        sum += __shfl_xor_sync(~0u, sum, o);
        ss  += __shfl_xor_sync(~0u, ss, o);
    }
    float mu = sum * (1.f / CDIM);
    float rs = rsqrtf(ss * (1.f / CDIM) - mu * mu + 1e-5f);
    float* orow = out + (size_t)t * CDIM;
    #pragma unroll
    for (int j = 0; j < 6; j++) {
        int c = j * 32 + lane;
        orow[c] = (v[j] - mu) * rs * g[c] + bt[c];
    }
}

// ---------------- launch ----------------
extern "C" void kernel_launch(void* const* d_in, const int* in_sizes, int n_in,
                              void* d_out, int out_size) {
    const float* x       = (const float*)d_in[0];
    const float* norm1_g = (const float*)d_in[1];
    const float* norm1_b = (const float*)d_in[2];
    const float* qkv_w   = (const float*)d_in[3];
    const float* qkv_b   = (const float*)d_in[4];
    const float* proj_w  = (const float*)d_in[5];
    const float* proj_b  = (const float*)d_in[6];
    const float* rpb     = (const float*)d_in[7];
    const float* temp    = (const float*)d_in[8];
    const float* norm2_g = (const float*)d_in[9];
    const float* norm2_b = (const float*)d_in[10];
    const float* fc1_w   = (const float*)d_in[11];
    const float* fc1_b   = (const float*)d_in[12];
    const float* fc2_w   = (const float*)d_in[13];
    const float* fc2_b   = (const float*)d_in[14];
    float* out = (float*)d_out;

    float *p_shortcut, *p_qkv, *p_attnout, *p_x2, *p_ln2, *p_hidden;
    cudaGetSymbolAddress((void**)&p_shortcut, g_shortcut);
    cudaGetSymbolAddress((void**)&p_qkv,      g_qkv);
    cudaGetSymbolAddress((void**)&p_attnout,  g_attnout);
    cudaGetSymbolAddress((void**)&p_x2,       g_x2);
    cudaGetSymbolAddress((void**)&p_ln2,      g_ln2);
    cudaGetSymbolAddress((void**)&p_hidden,   g_hidden);

    // 1) LN1 (+ NCHW -> token-major)
    ln1_kernel<<<TOK / 32, 256>>>(x, norm1_g, norm1_b);

    // 2) QKV (3xTF32 split)
    tgemm<0, true><<<dim3(TOK / 128, 576 / 64), 256>>>(
        p_shortcut, qkv_w, qkv_b, nullptr, p_qkv, TOK, 576, CDIM);

    // 3) windowed attention (tensor-core)
    attn_kernel<<<dim3(NWIN, HEADS), 256>>>(rpb, temp);

    // 4) proj + residual(shortcut) -> x2
    tgemm<2, false><<<dim3(TOK / 128, CDIM / 64), 256>>>(
        p_attnout, proj_w, proj_b, p_shortcut, p_x2, TOK, CDIM, CDIM);

    // 5) LN2
    ln2_kernel<<<TOK / 8, 256>>>(p_x2, norm2_g, norm2_b, p_ln2);

    // 6) fc1 + gelu
    tgemm<1, false><<<dim3(TOK / 128, HID / 64), 256>>>(
        p_ln2, fc1_w, fc1_b, nullptr, p_hidden, TOK, HID, CDIM);

    // 7) fc2 + residual(x2), fused transpose to (B,C,L)
    tgemm<3, false><<<dim3(TOK / 128, CDIM / 64), 256>>>(
        p_hidden, fc2_w, fc2_b, p_x2, out, TOK, CDIM, HID);
}

// round 11
// speedup vs baseline: 2.3790x; 1.0659x over previous
#include <cuda_runtime.h>
#include <math.h>
#include <stdint.h>

// ---------------- problem constants ----------------
#define BATCH 8
#define CDIM 192
#define HH 64
#define WW 64
#define LTOK 4096
#define TOK 32768
#define HEADS 6
#define HD 32
#define WS 8
#define NW 64
#define NWIN 512
#define INCC 16
#define HID 768

// ---------------- scratch ----------------
__device__ float g_shortcut[TOK * CDIM];
__device__ float g_qkv[TOK * 3 * CDIM];
__device__ float g_attnout[TOK * CDIM];
__device__ float g_x2[TOK * CDIM];
__device__ float g_ln2[TOK * CDIM];
__device__ float g_hidden[TOK * HID];

// ---------------- helpers ----------------
__device__ __forceinline__ uint32_t f2tf(float v) {
    uint32_t r;
    asm("cvt.rna.tf32.f32 %0, %1;" : "=r"(r) : "f"(v));
    return r;
}
__device__ __forceinline__ void mma8(float* c, const uint32_t* a, const uint32_t* b) {
    asm volatile(
        "mma.sync.aligned.m16n8k8.row.col.f32.tf32.tf32.f32 "
        "{%0,%1,%2,%3}, {%4,%5,%6,%7}, {%8,%9}, {%0,%1,%2,%3};"
        : "+f"(c[0]), "+f"(c[1]), "+f"(c[2]), "+f"(c[3])
        : "r"(a[0]), "r"(a[1]), "r"(a[2]), "r"(a[3]), "r"(b[0]), "r"(b[1]));
}
__device__ __forceinline__ void ldsm4(uint32_t* r, const float* p) {
    uint32_t a = (uint32_t)__cvta_generic_to_shared(p);
    asm volatile("ldmatrix.sync.aligned.m8n8.x4.shared.b16 {%0,%1,%2,%3}, [%4];"
                 : "=r"(r[0]), "=r"(r[1]), "=r"(r[2]), "=r"(r[3]) : "r"(a));
}
__device__ __forceinline__ void cp16(void* smem, const void* g) {
    uint32_t a = (uint32_t)__cvta_generic_to_shared(smem);
    asm volatile("cp.async.cg.shared.global [%0], [%1], 16;" :: "r"(a), "l"(g));
}
__device__ __forceinline__ void cp_commit() { asm volatile("cp.async.commit_group;"); }
template <int N>
__device__ __forceinline__ void cp_wait() { asm volatile("cp.async.wait_group %0;" :: "n"(N)); }

// ---------------- LN1: (B,C,H,W) -> token-major normalized ----------------
__global__ void ln1_kernel(const float* __restrict__ x,
                           const float* __restrict__ g,
                           const float* __restrict__ bt) {
    __shared__ float s[CDIM][33];
    __shared__ float s_mu[32], s_rs[32];
    int tile = blockIdx.x;
    int b = tile / (LTOK / 32);
    int l0 = (tile % (LTOK / 32)) * 32;
    const float* xb = x + (size_t)b * CDIM * LTOK;
    for (int idx = threadIdx.x; idx < CDIM * 32; idx += 256) {
        int c = idx >> 5, i = idx & 31;
        s[c][i] = xb[(size_t)c * LTOK + l0 + i];
    }
    __syncthreads();
    int warp = threadIdx.x >> 5, lane = threadIdx.x & 31;
    for (int i = warp; i < 32; i += 8) {
        float sum = 0.f, ss = 0.f;
        #pragma unroll
        for (int j = 0; j < 6; j++) {
            float v = s[j * 32 + lane][i];
            sum += v; ss += v * v;
        }
        #pragma unroll
        for (int o = 16; o; o >>= 1) {
            sum += __shfl_xor_sync(~0u, sum, o);
            ss  += __shfl_xor_sync(~0u, ss, o);
        }
        float mu = sum * (1.f / CDIM);
        float var = ss * (1.f / CDIM) - mu * mu;
        if (lane == 0) { s_mu[i] = mu; s_rs[i] = rsqrtf(var + 1e-5f); }
    }
    __syncthreads();
    float* out = g_shortcut + ((size_t)b * LTOK + l0) * CDIM;
    for (int idx = threadIdx.x; idx < 32 * CDIM; idx += 256) {
        int i = idx / CDIM, c = idx % CDIM;
        out[(size_t)i * CDIM + c] = (s[c][i] - s_mu[i]) * s_rs[i] * g[c] + bt[c];
    }
}

// ---------------- pipelined tensor-core GEMM, ldmatrix fragments -------------
// EPI: 0 plain, 1 gelu, 2 +R, 3 +R then write transposed (B,C,L).
// SPLIT: 3xTF32 hi/lo (fp32-accurate).
template <int EPI, bool SPLIT>
__global__ void __launch_bounds__(256)
tgemm(const float* __restrict__ A, const float* __restrict__ Wt,
      const float* __restrict__ bias, const float* __restrict__ R,
      float* __restrict__ Cout, int M, int Nn, int K) {
    constexpr int BM = 128, BN = 64, BK = 16, ST = 20, STG = 3;
    __shared__ float As[STG][BM * ST];
    __shared__ float Bs[STG][BN * ST];

    int bm = blockIdx.x * BM, bn = blockIdx.y * BN;
    int tid = threadIdx.x, lane = tid & 31, warp = tid >> 5;
    int wm = (warp >> 1) * 32, wn = (warp & 1) * 32;
    int g = lane >> 2, tg = lane & 3;
    int l15 = lane & 15, lhi = lane >> 4;          // A-frag addressing
    int l7 = (lane & 7) + 8 * (lane >> 4);         // B-frag row
    int bko = 4 * ((lane >> 3) & 1);               // B-frag k offset

    float acc[2][4][4] = {};
    int KT = K / BK;

    auto load_stage = [&](int s, int k0) {
        #pragma unroll
        for (int t = tid; t < BM * (BK / 4); t += 256) {
            int row = t >> 2, c4 = t & 3;
            cp16(&As[s][row * ST + c4 * 4], A + (size_t)(bm + row) * K + k0 + c4 * 4);
        }
        {
            int row = tid >> 2, c4 = tid & 3;
            cp16(&Bs[s][row * ST + c4 * 4], Wt + (size_t)(bn + row) * K + k0 + c4 * 4);
        }
    };

    #pragma unroll
    for (int s = 0; s < STG - 1; s++) {
        if (s < KT) load_stage(s, s * BK);
        cp_commit();
    }

    for (int kt = 0; kt < KT; kt++) {
        cp_wait<STG - 2>();
        __syncthreads();
        int pf = kt + STG - 1;
        if (pf < KT) load_stage(pf % STG, pf * BK);
        cp_commit();

        const float* as = As[kt % STG];
        const float* bs = Bs[kt % STG];
        #pragma unroll
        for (int ks = 0; ks < 2; ks++) {
            int k = ks * 8;
            uint32_t ar[2][4], br[2][4];
            #pragma unroll
            for (int mi = 0; mi < 2; mi++)
                ldsm4(ar[mi], &as[(wm + mi * 16 + l15) * ST + k + 4 * lhi]);
            #pragma unroll
            for (int nb = 0; nb < 2; nb++)
                ldsm4(br[nb], &bs[(wn + nb * 16 + l7) * ST + k + bko]);

            uint32_t ah[2][4], al[2][4], bh[2][4], bl[2][4];
            if (SPLIT) {
                #pragma unroll
                for (int mi = 0; mi < 2; mi++)
                    #pragma unroll
                    for (int j = 0; j < 4; j++) {
                        float v = __uint_as_float(ar[mi][j]);
                        ah[mi][j] = f2tf(v);
                        al[mi][j] = f2tf(v - __uint_as_float(ah[mi][j]));
                    }
                #pragma unroll
                for (int nb = 0; nb < 2; nb++)
                    #pragma unroll
                    for (int j = 0; j < 4; j++) {
                        float v = __uint_as_float(br[nb][j]);
                        bh[nb][j] = f2tf(v);
                        bl[nb][j] = f2tf(v - __uint_as_float(bh[nb][j]));
                    }
            }
            #pragma unroll
            for (int mi = 0; mi < 2; mi++)
                #pragma unroll
                for (int ni = 0; ni < 4; ni++) {
                    int nb = ni >> 1, e = (ni & 1) * 2;
                    if (SPLIT) {
                        uint32_t b2h[2] = {bh[nb][e], bh[nb][e + 1]};
                        uint32_t b2l[2] = {bl[nb][e], bl[nb][e + 1]};
                        mma8(acc[mi][ni], ah[mi], b2h);
                        mma8(acc[mi][ni], ah[mi], b2l);
                        mma8(acc[mi][ni], al[mi], b2h);
                    } else {
                        uint32_t b2[2] = {br[nb][e], br[nb][e + 1]};
                        mma8(acc[mi][ni], ar[mi], b2);
                    }
                }
        }
    }

    // epilogue
    #pragma unroll
    for (int mi = 0; mi < 2; mi++) {
        #pragma unroll
        for (int ni = 0; ni < 4; ni++) {
            int r0 = bm + wm + mi * 16 + g;
            int c = bn + wn + ni * 8 + tg * 2;
            float bz0 = bias[c], bz1 = bias[c + 1];
            #pragma unroll
            for (int rr = 0; rr < 2; rr++) {
                int m = r0 + rr * 8;
                float v0 = acc[mi][ni][rr * 2 + 0] + bz0;
                float v1 = acc[mi][ni][rr * 2 + 1] + bz1;
                if (EPI == 1) {
                    v0 = 0.5f * v0 * (1.f + erff(v0 * 0.70710678118654752f));
                    v1 = 0.5f * v1 * (1.f + erff(v1 * 0.70710678118654752f));
                }
                if (EPI == 2 || EPI == 3) {
                    v0 += R[(size_t)m * Nn + c];
                    v1 += R[(size_t)m * Nn + c + 1];
                }
                if (EPI == 3) {
                    int b = m >> 12, l = m & 4095;
                    Cout[((size_t)b * CDIM + c) * LTOK + l] = v0;
                    Cout[((size_t)b * CDIM + c + 1) * LTOK + l] = v1;
                } else {
                    Cout[(size_t)m * Nn + c] = v0;
                    Cout[(size_t)m * Nn + c + 1] = v1;
                }
            }
        }
    }
}

// ---------------- tensor-core window attention: block per (window, head) -----
// S = l2n(Q) @ l2n(K)^T * temp via split-3xTF32 (fp32-accurate for stable topk)
// O = P @ V via rna-tf32 mma. Top-16 threshold: 8 lanes/row, 4 rows/warp.
__global__ void __launch_bounds__(256) attn_kernel(const float* __restrict__ rpb_table,
                                                   const float* __restrict__ temperature) {
    __shared__ float qs[NW * 36], ks[NW * 36];
    __shared__ float vst[HD * 68];       // V transposed: [d][key]
    __shared__ float at[NW * 68];        // V staging, then S / P
    __shared__ float kths[NW];
    int win = blockIdx.x, h = blockIdx.y;
    int b = win >> 6;
    int wy = (win & 63) >> 3, wx = win & 7;
    int tid = threadIdx.x, lane = tid & 31, warp = tid >> 5;
    int g = lane >> 2, tg = lane & 3;
    int l15 = lane & 15, lhi = lane >> 4;
    int l7 = (lane & 7) + 8 * (lane >> 4);
    int bko = 4 * ((lane >> 3) & 1);

    // load q,k ([n][d], stride 36) + v into at ([n][d], stride 68)
    for (int idx = tid; idx < NW * HD; idx += 256) {
        int n = idx >> 5, d = idx & 31;
        int y = wy * 8 + (n >> 3), xx = wx * 8 + (n & 7);
        size_t t = (size_t)b * LTOK + y * WW + xx;
        const float* base = g_qkv + t * (3 * CDIM) + h * HD + d;
        qs[n * 36 + d] = base[0];
        ks[n * 36 + d] = base[CDIM];
        at[n * 68 + d] = base[2 * CDIM];
    }
    __syncthreads();

    // l2-normalize q,k rows
    for (int r = warp; r < NW; r += 8) {
        float qv = qs[r * 36 + lane], kv = ks[r * 36 + lane];
        float sq = qv * qv, sk = kv * kv;
        #pragma unroll
        for (int o = 16; o; o >>= 1) {
            sq += __shfl_xor_sync(~0u, sq, o);
            sk += __shfl_xor_sync(~0u, sk, o);
        }
        qs[r * 36 + lane] = qv / fmaxf(sqrtf(sq), 1e-12f);
        ks[r * 36 + lane] = kv / fmaxf(sqrtf(sk), 1e-12f);
    }
    // transpose v: at[n][d] -> vst[d][n]
    for (int idx = tid; idx < NW * HD; idx += 256) {
        int n = idx & 63, d = idx >> 6;
        vst[d * 68 + n] = at[n * 68 + d];
    }
    __syncthreads();

    float temp = temperature[h];
    // S mma: warp tile m16 x n32
    {
        int wm = (warp >> 1) * 16, wn = (warp & 1) * 32;
        float acc[4][4] = {};
        #pragma unroll
        for (int kc = 0; kc < 4; kc++) {
            int k = kc * 8;
            uint32_t ar[4], br[2][4];
            ldsm4(ar, &qs[(wm + l15) * 36 + k + 4 * lhi]);
            #pragma unroll
            for (int nb = 0; nb < 2; nb++)
                ldsm4(br[nb], &ks[(wn + nb * 16 + l7) * 36 + k + bko]);
            uint32_t ah[4], al[4], bh[2][4], bl[2][4];
            #pragma unroll
            for (int j = 0; j < 4; j++) {
                float v = __uint_as_float(ar[j]);
                ah[j] = f2tf(v);
                al[j] = f2tf(v - __uint_as_float(ah[j]));
            }
            #pragma unroll
            for (int nb = 0; nb < 2; nb++)
                #pragma unroll
                for (int j = 0; j < 4; j++) {
                    float v = __uint_as_float(br[nb][j]);
                    bh[nb][j] = f2tf(v);
                    bl[nb][j] = f2tf(v - __uint_as_float(bh[nb][j]));
                }
            #pragma unroll
            for (int ni = 0; ni < 4; ni++) {
                int nb = ni >> 1, e = (ni & 1) * 2;
                uint32_t b2h[2] = {bh[nb][e], bh[nb][e + 1]};
                uint32_t b2l[2] = {bl[nb][e], bl[nb][e + 1]};
                mma8(acc[ni], ah, b2h);
                mma8(acc[ni], ah, b2l);
                mma8(acc[ni], al, b2h);
            }
        }
        #pragma unroll
        for (int ni = 0; ni < 4; ni++) {
            float* p0 = &at[(wm + g) * 68 + wn + ni * 8 + tg * 2];
            float* p1 = &at[(wm + g + 8) * 68 + wn + ni * 8 + tg * 2];
            p0[0] = acc[ni][0] * temp; p0[1] = acc[ni][1] * temp;
            p1[0] = acc[ni][2] * temp; p1[1] = acc[ni][3] * temp;
        }
    }
    __syncthreads();

    // top-16 threshold per row: 8 lanes per row, 4 rows per warp, 2 batches.
    // Extraction semantics identical to serial topk (remove one max instance
    // per iteration; kth = 16th extracted max).
    {
        int group = lane >> 3, pos = lane & 7;
        unsigned gmask = 0xFFu << (group * 8);
        #pragma unroll
        for (int rb = 0; rb < 2; rb++) {
            int row = warp + 8 * (rb * 4 + group);
            float a[8];
            #pragma unroll
            for (int t = 0; t < 8; t++) a[t] = at[row * 68 + t * 8 + pos];
            float kth = 0.f;
            #pragma unroll
            for (int it = 0; it < INCC; it++) {
                float m = a[0];
                #pragma unroll
                for (int t = 1; t < 8; t++) m = fmaxf(m, a[t]);
                float gm = m;
                #pragma unroll
                for (int o = 4; o; o >>= 1) gm = fmaxf(gm, __shfl_xor_sync(~0u, gm, o));
                kth = gm;
                unsigned bal = __ballot_sync(~0u, m == gm) & gmask;
                int src = __ffs(bal) - 1;
                if (lane == src) {
                    bool done = false;
                    #pragma unroll
                    for (int t = 0; t < 8; t++)
                        if (!done && a[t] == gm) { a[t] = -1e30f; done = true; }
                }
            }
            if (pos == 0) kths[row] = kth;
        }
    }
    __syncthreads();

    // per-row: mask below kth, +rpb, softmax (one warp per row, 2 keys/lane)
    for (int r = warp; r < NW; r += 8) {
        float a0 = at[r * 68 + lane], a1 = at[r * 68 + lane + 32];
        float kth = kths[r];
        int ry = r >> 3, rx = r & 7;
        int j0 = lane, j1 = lane + 32;
        int i0 = ((ry - (j0 >> 3) + 7) * 15 + (rx - (j0 & 7) + 7)) * HEADS + h;
        int i1 = ((ry - (j1 >> 3) + 7) * 15 + (rx - (j1 & 7) + 7)) * HEADS + h;
        float v0 = (a0 >= kth ? a0 : -100.f) + rpb_table[i0];
        float v1 = (a1 >= kth ? a1 : -100.f) + rpb_table[i1];
        float m = fmaxf(v0, v1);
        #pragma unroll
        for (int o = 16; o; o >>= 1) m = fmaxf(m, __shfl_xor_sync(~0u, m, o));
        float e0 = __expf(v0 - m), e1 = __expf(v1 - m);
        float s = e0 + e1;
        #pragma unroll
        for (int o = 16; o; o >>= 1) s += __shfl_xor_sync(~0u, s, o);
        float inv = 1.f / s;
        at[r * 68 + lane] = e0 * inv;
        at[r * 68 + lane + 32] = e1 * inv;
    }
    __syncthreads();

    // O = P @ V : warp tile m16 x n16, k=64
    {
        int mt = warp >> 1, nh = (warp & 1) * 16;
        float acc[2][4] = {};
        #pragma unroll
        for (int kc = 0; kc < 8; kc++) {
            int k = kc * 8;
            uint32_t ar[4], br[4], af[4], bf[4];
            ldsm4(ar, &at[(mt * 16 + l15) * 68 + k + 4 * lhi]);
            ldsm4(br, &vst[(nh + l7) * 68 + k + bko]);
            #pragma unroll
            for (int j = 0; j < 4; j++) {
                af[j] = f2tf(__uint_as_float(ar[j]));
                bf[j] = f2tf(__uint_as_float(br[j]));
            }
            uint32_t b20[2] = {bf[0], bf[1]};
            uint32_t b21[2] = {bf[2], bf[3]};
            mma8(acc[0], af, b20);
            mma8(acc[1], af, b21);
        }
        #pragma unroll
        for (int ni = 0; ni < 2; ni++) {
            int c = h * HD + nh + ni * 8 + tg * 2;
            #pragma unroll
            for (int rr = 0; rr < 2; rr++) {
                int m = mt * 16 + g + rr * 8;
                int y = wy * 8 + (m >> 3), xx = wx * 8 + (m & 7);
                size_t t = (size_t)b * LTOK + y * WW + xx;
                g_attnout[t * CDIM + c]     = acc[ni][rr * 2];
                g_attnout[t * CDIM + c + 1] = acc[ni][rr * 2 + 1];
            }
        }
    }
}

// ---------------- LN2 ----------------
__global__ void ln2_kernel(const float* __restrict__ xin,
                           const float* __restrict__ g,
                           const float* __restrict__ bt,
                           float* __restrict__ out) {
    int t = blockIdx.x * 8 + (threadIdx.x >> 5);
    int lane = threadIdx.x & 31;
    const float* row = xin + (size_t)t * CDIM;
    float v[6]; float sum = 0.f, ss = 0.f;
    #pragma unroll
    for (int j = 0; j < 6; j++) {
        v[j] = row[j * 32 + lane];
        sum += v[j]; ss += v[j] * v[j];
    }
    #pragma unroll
    for (int o = 16; o; o >>= 1) {
        sum += __shfl_xor_sync(~0u, sum, o);
        ss  += __shfl_xor_sync(~0u, ss, o);
    }
    float mu = sum * (1.f / CDIM);
    float rs = rsqrtf(ss * (1.f / CDIM) - mu * mu + 1e-5f);
    float* orow = out + (size_t)t * CDIM;
    #pragma unroll
    for (int j = 0; j < 6; j++) {
        int c = j * 32 + lane;
        orow[c] = (v[j] - mu) * rs * g[c] + bt[c];
    }
}

// ---------------- launch ----------------
extern "C" void kernel_launch(void* const* d_in, const int* in_sizes, int n_in,
                              void* d_out, int out_size) {
    const float* x       = (const float*)d_in[0];
    const float* norm1_g = (const float*)d_in[1];
    const float* norm1_b = (const float*)d_in[2];
    const float* qkv_w   = (const float*)d_in[3];
    const float* qkv_b   = (const float*)d_in[4];
    const float* proj_w  = (const float*)d_in[5];
    const float* proj_b  = (const float*)d_in[6];
    const float* rpb     = (const float*)d_in[7];
    const float* temp    = (const float*)d_in[8];
    const float* norm2_g = (const float*)d_in[9];
    const float* norm2_b = (const float*)d_in[10];
    const float* fc1_w   = (const float*)d_in[11];
    const float* fc1_b   = (const float*)d_in[12];
    const float* fc2_w   = (const float*)d_in[13];
    const float* fc2_b   = (const float*)d_in[14];
    float* out = (float*)d_out;

    float *p_shortcut, *p_qkv, *p_attnout, *p_x2, *p_ln2, *p_hidden;
    cudaGetSymbolAddress((void**)&p_shortcut, g_shortcut);
    cudaGetSymbolAddress((void**)&p_qkv,      g_qkv);
    cudaGetSymbolAddress((void**)&p_attnout,  g_attnout);
    cudaGetSymbolAddress((void**)&p_x2,       g_x2);
    cudaGetSymbolAddress((void**)&p_ln2,      g_ln2);
    cudaGetSymbolAddress((void**)&p_hidden,   g_hidden);

    // 1) LN1 (+ NCHW -> token-major)
    ln1_kernel<<<TOK / 32, 256>>>(x, norm1_g, norm1_b);

    // 2) QKV (3xTF32 split)
    tgemm<0, true><<<dim3(TOK / 128, 576 / 64), 256>>>(
        p_shortcut, qkv_w, qkv_b, nullptr, p_qkv, TOK, 576, CDIM);

    // 3) windowed attention (tensor-core)
    attn_kernel<<<dim3(NWIN, HEADS), 256>>>(rpb, temp);

    // 4) proj + residual(shortcut) -> x2
    tgemm<2, false><<<dim3(TOK / 128, CDIM / 64), 256>>>(
        p_attnout, proj_w, proj_b, p_shortcut, p_x2, TOK, CDIM, CDIM);

    // 5) LN2
    ln2_kernel<<<TOK / 8, 256>>>(p_x2, norm2_g, norm2_b, p_ln2);

    // 6) fc1 + gelu
    tgemm<1, false><<<dim3(TOK / 128, HID / 64), 256>>>(
        p_ln2, fc1_w, fc1_b, nullptr, p_hidden, TOK, HID, CDIM);

    // 7) fc2 + residual(x2), fused transpose to (B,C,L)
    tgemm<3, false><<<dim3(TOK / 128, CDIM / 64), 256>>>(
        p_hidden, fc2_w, fc2_b, p_x2, out, TOK, CDIM, HID);
}